// round 12
// baseline (speedup 1.0000x reference)
#include <cuda_runtime.h>
#include <cuda_fp16.h>
#include <cstdint>
#include <math.h>

#define N_B   32
#define C_IN  128
#define L_LEN 512
#define C_P   64
#define P_NUM 2000
#define P_PAD 2048
#define N_CLS 200
#define EPS   1e-4f

// ---------------- scratch (no cudaMalloc allowed) --------------------------
__device__ float g_p2[P_PAD];                // ||proto||^2
__device__ float g_x2[N_B * L_LEN];          // per-position sum f^2
__device__ float g_w1t[C_IN * C_P];          // W1^T [c][o]
__device__ float g_w2t[C_P * C_P];           // W2^T [c][o]
__device__ float g_act[N_B * P_NUM];         // prototype activations
// fp16 split operands, K-major rows of 64 halves = 128B = 8 uint4
__device__ uint4 g_ph[P_PAD * 8];            // proto hi  [p][k]
__device__ uint4 g_pl[P_PAD * 8];            // proto lo
__device__ uint4 g_fh[N_B * L_LEN * 8];      // f hi      [n*l][k]
__device__ uint4 g_fl[N_B * L_LEN * 8];      // f lo

// ---------------- helpers ---------------------------------------------------
__device__ __forceinline__ uint32_t smem_u32(const void* p) {
    uint32_t a;
    asm("{ .reg .u64 t; cvta.to.shared.u64 t, %1; cvt.u32.u64 %0, t; }"
        : "=r"(a) : "l"(p));
    return a;
}
__device__ __forceinline__ void ldmx4(uint32_t* r, uint32_t addr) {
    asm volatile("ldmatrix.sync.aligned.m8n8.x4.shared.b16 {%0,%1,%2,%3}, [%4];"
                 : "=r"(r[0]), "=r"(r[1]), "=r"(r[2]), "=r"(r[3]) : "r"(addr));
}
__device__ __forceinline__ void mma16816(float* c, const uint32_t* a, const uint32_t* b) {
    asm volatile("mma.sync.aligned.m16n8k16.row.col.f32.f16.f16.f32 "
                 "{%0,%1,%2,%3}, {%4,%5,%6,%7}, {%8,%9}, {%0,%1,%2,%3};"
                 : "+f"(c[0]), "+f"(c[1]), "+f"(c[2]), "+f"(c[3])
                 : "r"(a[0]), "r"(a[1]), "r"(a[2]), "r"(a[3]), "r"(b[0]), "r"(b[1]));
}
__device__ __forceinline__ uint32_t pack_half2(float v0, float v1) {
    __half h0 = __float2half_rn(v0), h1 = __float2half_rn(v1);
    return (uint32_t)__half_as_ushort(h0) | ((uint32_t)__half_as_ushort(h1) << 16);
}
#define CP_ASYNC16(dst, src) \
    asm volatile("cp.async.cg.shared.global [%0], [%1], 16;" :: "r"(dst), "l"(src))
#define CP_COMMIT() asm volatile("cp.async.commit_group;")
#define CP_WAIT(n)  asm volatile("cp.async.wait_group %0;" :: "n"(n))

// ---------------------------------------------------------------------------
// Prep: W transposes, proto norms, proto fp16 hi/lo split
// ---------------------------------------------------------------------------
__global__ void prep_kernel(const float* __restrict__ W1,
                            const float* __restrict__ W2,
                            const float* __restrict__ proto) {
    int stride = gridDim.x * blockDim.x;
    int tid = blockIdx.x * blockDim.x + threadIdx.x;
    for (int e = tid; e < C_IN * C_P; e += stride) {
        int c = e >> 6, o = e & 63;
        g_w1t[e] = W1[o * C_IN + c];
    }
    for (int e = tid; e < C_P * C_P; e += stride) {
        int c = e >> 6, o = e & 63;
        g_w2t[e] = W2[o * C_P + c];
    }
    for (int p = tid; p < P_PAD; p += stride) {
        float s = 0.f;
        if (p < P_NUM) {
            #pragma unroll 8
            for (int c = 0; c < C_P; c++) {
                float v = proto[p * C_P + c];
                s += v * v;
            }
        }
        g_p2[p] = s;
    }
    for (int e = tid; e < P_PAD * 8; e += stride) {
        int p = e >> 3, u = e & 7;
        uint32_t hw[4], lw[4];
        #pragma unroll
        for (int j = 0; j < 4; j++) {
            float v0 = 0.f, v1 = 0.f;
            if (p < P_NUM) {
                v0 = proto[p * C_P + u * 8 + j * 2];
                v1 = proto[p * C_P + u * 8 + j * 2 + 1];
            }
            __half h0 = __float2half_rn(v0), h1 = __float2half_rn(v1);
            float r0 = v0 - __half2float(h0), r1 = v1 - __half2float(h1);
            hw[j] = (uint32_t)__half_as_ushort(h0) | ((uint32_t)__half_as_ushort(h1) << 16);
            lw[j] = pack_half2(r0, r1);
        }
        g_ph[e] = make_uint4(hw[0], hw[1], hw[2], hw[3]);
        g_pl[e] = make_uint4(lw[0], lw[1], lw[2], lw[3]);
    }
}

// ---------------------------------------------------------------------------
// addon: fused conv1(relu) -> conv2(sigmoid) -> fp16 hi/lo pack + x2
// grid (L/32 = 16, N_B), 256 threads. All intermediates stay in SMEM.
// Dynamic SMEM layout (bytes):
//   xs  [128][32] @ 0       (16384)
//   w1s [128][64] @ 16384   (32768)
//   hs  [ 64][32] @ 49152   ( 8192)
//   w2s [ 64][64] @ 57344   (16384)
//   fs  [ 64][32] @ 73728   ( 8192)   total 81920
// ---------------------------------------------------------------------------
#define AD_XS  0
#define AD_W1  16384
#define AD_HS  49152
#define AD_W2  57344
#define AD_FS  73728
#define AD_TOT 81920

__global__ void __launch_bounds__(256) addon_kernel(const float* __restrict__ x,
                                                    const float* __restrict__ b1,
                                                    const float* __restrict__ b2) {
    extern __shared__ char sm[];
    float (*xs)[32]  = (float (*)[32])(sm + AD_XS);
    float (*w1s)[64] = (float (*)[64])(sm + AD_W1);
    float (*hs)[32]  = (float (*)[32])(sm + AD_HS);
    float (*w2s)[64] = (float (*)[64])(sm + AD_W2);
    float (*fs)[32]  = (float (*)[32])(sm + AD_FS);

    int n  = blockIdx.y;
    int l0 = blockIdx.x * 32;
    int tid = threadIdx.x;
    int tl = tid & 15, to = tid >> 4;

    for (int e = tid; e < C_IN * 32; e += 256) {
        int c = e >> 5, l = e & 31;
        xs[c][l] = x[(n * C_IN + c) * L_LEN + l0 + l];
    }
    for (int e = tid; e < C_IN * C_P; e += 256)
        w1s[e >> 6][e & 63] = g_w1t[e];
    for (int e = tid; e < C_P * C_P; e += 256)
        w2s[e >> 6][e & 63] = g_w2t[e];
    __syncthreads();

    // phase 1: h = relu(W1 @ x + b1)
    {
        float acc[4][2] = {};
        #pragma unroll
        for (int k = 0; k < C_IN; k++) {
            float4 a = *(const float4*)&w1s[k][to * 4];
            float2 b = *(const float2*)&xs[k][tl * 2];
            acc[0][0] += a.x * b.x; acc[0][1] += a.x * b.y;
            acc[1][0] += a.y * b.x; acc[1][1] += a.y * b.y;
            acc[2][0] += a.z * b.x; acc[2][1] += a.z * b.y;
            acc[3][0] += a.w * b.x; acc[3][1] += a.w * b.y;
        }
        float4 bv = *(const float4*)&b1[to * 4];
        float bb[4] = {bv.x, bv.y, bv.z, bv.w};
        #pragma unroll
        for (int i = 0; i < 4; i++) {
            hs[to * 4 + i][tl * 2]     = fmaxf(acc[i][0] + bb[i], 0.f);
            hs[to * 4 + i][tl * 2 + 1] = fmaxf(acc[i][1] + bb[i], 0.f);
        }
    }
    __syncthreads();

    // phase 2: f = sigmoid(W2 @ h + b2)
    {
        float acc[4][2] = {};
        #pragma unroll
        for (int k = 0; k < C_P; k++) {
            float4 a = *(const float4*)&w2s[k][to * 4];
            float2 b = *(const float2*)&hs[k][tl * 2];
            acc[0][0] += a.x * b.x; acc[0][1] += a.x * b.y;
            acc[1][0] += a.y * b.x; acc[1][1] += a.y * b.y;
            acc[2][0] += a.z * b.x; acc[2][1] += a.z * b.y;
            acc[3][0] += a.w * b.x; acc[3][1] += a.w * b.y;
        }
        float4 bv = *(const float4*)&b2[to * 4];
        float bb[4] = {bv.x, bv.y, bv.z, bv.w};
        #pragma unroll
        for (int i = 0; i < 4; i++) {
            float z0 = acc[i][0] + bb[i];
            float z1 = acc[i][1] + bb[i];
            fs[to * 4 + i][tl * 2]     = 1.f / (1.f + __expf(-z0));
            fs[to * 4 + i][tl * 2 + 1] = 1.f / (1.f + __expf(-z1));
        }
    }
    __syncthreads();

    // phase 3a: pack to fp16 hi/lo rows — all 256 threads, one (l,u) each
    {
        int l = tid & 31, u = tid >> 5;
        uint32_t hw[4], lw[4];
        #pragma unroll
        for (int j = 0; j < 4; j++) {
            float v0 = fs[u * 8 + j * 2][l];
            float v1 = fs[u * 8 + j * 2 + 1][l];
            __half h0 = __float2half_rn(v0), h1 = __float2half_rn(v1);
            float r0 = v0 - __half2float(h0), r1 = v1 - __half2float(h1);
            hw[j] = (uint32_t)__half_as_ushort(h0) |
                    ((uint32_t)__half_as_ushort(h1) << 16);
            lw[j] = pack_half2(r0, r1);
        }
        g_fh[(n * L_LEN + l0 + l) * 8 + u] = make_uint4(hw[0], hw[1], hw[2], hw[3]);
        g_fl[(n * L_LEN + l0 + l) * 8 + u] = make_uint4(lw[0], lw[1], lw[2], lw[3]);
    }

    // phase 3b: x2 per l (32 threads; deterministic fixed-order sum)
    if (tid < 32) {
        int l = tid;
        float s = 0.f;
        #pragma unroll
        for (int c = 0; c < C_P; c++) {
            float v = fs[c][l];
            s = fmaf(v, v, s);
        }
        g_x2[n * L_LEN + l0 + l] = s;
    }
}

// ---------------------------------------------------------------------------
// l2min via mma.sync: split-fp16 (pH·fH + pH·fL + pL·fH) + min over L
// grid (16, 32), 256 threads = 8 warps; block 128p x 128l, K=64
// cp.async 2-stage pipeline on B tiles.
// SMEM: AH @0, AL @18432, B stages @36864 (2 x 36864: BH+BL), minb @110592
// ---------------------------------------------------------------------------
#define ROW_B   144
#define SM_AH   0
#define SM_AL   18432
#define SM_B    36864
#define STAGE_B 36864
#define SM_MINB 110592
#define SM_TOT  111616

__global__ void __launch_bounds__(256, 1) l2min_mma_kernel(float* __restrict__ mind_out) {
    extern __shared__ char smem[];
    uint32_t sb = smem_u32(smem);
    float* minb = (float*)(smem + SM_MINB);   // [128][2]

    int tid = threadIdx.x;
    int lane = tid & 31, wid = tid >> 5;
    int warpP = wid & 3, warpL = wid >> 2;    // 4 p-warps x 2 l-warps
    int pt = blockIdx.x, n = blockIdx.y;

    // ---- A tiles (proto hi/lo): plain loads ----
    for (int e = tid; e < 1024; e += 256) {
        int row = e >> 3, u = e & 7;
        int off = row * ROW_B + u * 16;
        *(uint4*)(smem + SM_AH + off) = g_ph[(pt * 128 + row) * 8 + u];
        *(uint4*)(smem + SM_AL + off) = g_pl[(pt * 128 + row) * 8 + u];
    }

    // ---- B stage loader: 2048 x 16B via cp.async ----
    auto load_stage = [&](int lc, int st) {
        uint32_t dbase = sb + SM_B + st * STAGE_B;
        #pragma unroll
        for (int i = 0; i < 8; i++) {
            int e = tid + i * 256;
            int sel = e >> 10;            // 0 = hi, 1 = lo
            int e2 = e & 1023;
            int row = e2 >> 3, u = e2 & 7;
            uint32_t dst = dbase + sel * 18432 + row * ROW_B + u * 16;
            const uint4* src = (sel ? g_fl : g_fh) +
                               (n * L_LEN + lc * 128 + row) * 8 + u;
            CP_ASYNC16(dst, src);
        }
        CP_COMMIT();
    };
    load_stage(0, 0);

    // ldmatrix per-thread offsets
    int aRow = warpP * 32 + (lane & 7) + ((lane >> 3) & 1) * 8;
    int aCol = ((lane >> 4) & 1) * 8;
    uint32_t aOff = (uint32_t)(aRow * ROW_B + aCol * 2);
    int bRow = warpL * 64 + (lane & 7) + ((lane >> 4) & 1) * 8;
    int bCol = ((lane >> 3) & 1) * 8;
    uint32_t bOff = (uint32_t)(bRow * ROW_B + bCol * 2);

    float mind[2][2];
    mind[0][0] = mind[0][1] = mind[1][0] = mind[1][1] = 1e30f;

    for (int lc = 0; lc < 4; lc++) {
        if (lc < 3) { load_stage(lc + 1, (lc + 1) & 1); CP_WAIT(1); }
        else        { CP_WAIT(0); }
        __syncthreads();   // stage lc visible to all (also A on first iter)

        uint32_t sBH = sb + SM_B + (lc & 1) * STAGE_B;
        uint32_t sBL = sBH + 18432;

        float acc[2][8][4];
        #pragma unroll
        for (int mi = 0; mi < 2; mi++)
            #pragma unroll
            for (int ni = 0; ni < 8; ni++)
                #pragma unroll
                for (int q = 0; q < 4; q++) acc[mi][ni][q] = 0.f;

        #pragma unroll
        for (int ks = 0; ks < 4; ks++) {
            uint32_t ah[2][4], al[2][4];
            #pragma unroll
            for (int mi = 0; mi < 2; mi++) {
                uint32_t ao = aOff + mi * 16 * ROW_B + ks * 32;
                ldmx4(ah[mi], sb + SM_AH + ao);
                ldmx4(al[mi], sb + SM_AL + ao);
            }
            uint32_t bh[8][2], bl[8][2];
            #pragma unroll
            for (int nj = 0; nj < 4; nj++) {
                uint32_t bo = bOff + nj * 16 * ROW_B + ks * 32;
                uint32_t t[4];
                ldmx4(t, sBH + bo);
                bh[nj * 2][0] = t[0]; bh[nj * 2][1] = t[1];
                bh[nj * 2 + 1][0] = t[2]; bh[nj * 2 + 1][1] = t[3];
                ldmx4(t, sBL + bo);
                bl[nj * 2][0] = t[0]; bl[nj * 2][1] = t[1];
                bl[nj * 2 + 1][0] = t[2]; bl[nj * 2 + 1][1] = t[3];
            }
            #pragma unroll
            for (int mi = 0; mi < 2; mi++)
                #pragma unroll
                for (int ni = 0; ni < 8; ni++) {
                    mma16816(acc[mi][ni], ah[mi], bh[ni]);
                    mma16816(acc[mi][ni], ah[mi], bl[ni]);
                    mma16816(acc[mi][ni], al[mi], bh[ni]);
                }
        }

        // fold min_l(x2 - 2*xp)
        #pragma unroll
        for (int ni = 0; ni < 8; ni++) {
            float2 xv = __ldg((const float2*)&g_x2[n * L_LEN + lc * 128 +
                                                   warpL * 64 + ni * 8 + (lane & 3) * 2]);
            #pragma unroll
            for (int mi = 0; mi < 2; mi++) {
                float d0 = fmaf(-2.f, acc[mi][ni][0], xv.x);
                float d1 = fmaf(-2.f, acc[mi][ni][1], xv.y);
                float d2 = fmaf(-2.f, acc[mi][ni][2], xv.x);
                float d3 = fmaf(-2.f, acc[mi][ni][3], xv.y);
                mind[mi][0] = fminf(mind[mi][0], fminf(d0, d1));
                mind[mi][1] = fminf(mind[mi][1], fminf(d2, d3));
            }
        }
        __syncthreads();   // all reads of stage lc done before it is refilled
    }

    #pragma unroll
    for (int mi = 0; mi < 2; mi++)
        #pragma unroll
        for (int rh = 0; rh < 2; rh++) {
            float v = mind[mi][rh];
            v = fminf(v, __shfl_xor_sync(0xffffffffu, v, 1));
            v = fminf(v, __shfl_xor_sync(0xffffffffu, v, 2));
            mind[mi][rh] = v;
        }
    if ((lane & 3) == 0) {
        int rbase = warpP * 32 + (lane >> 2);
        minb[(rbase +  0) * 2 + warpL] = mind[0][0];
        minb[(rbase +  8) * 2 + warpL] = mind[0][1];
        minb[(rbase + 16) * 2 + warpL] = mind[1][0];
        minb[(rbase + 24) * 2 + warpL] = mind[1][1];
    }
    __syncthreads();

    if (tid < 128) {
        float m = fminf(minb[tid * 2], minb[tid * 2 + 1]);
        float p2v = g_p2[pt * 128 + tid];
        float d = fmaxf(m + p2v, 0.f);
        int p = pt * 128 + tid;
        if (p < P_NUM) {
            if (mind_out) mind_out[n * P_NUM + p] = d;
            g_act[n * P_NUM + p] = logf((d + 1.f) / (d + EPS));
        }
    }
}

// ---------------------------------------------------------------------------
// logits: 25 blocks x 8 classes; w tile in SMEM, loop n inside
// ---------------------------------------------------------------------------
__global__ void __launch_bounds__(256) logits_kernel(const float* __restrict__ lw,
                                                     float* __restrict__ out) {
    extern __shared__ float ws[];   // [8][2000]
    int tid = threadIdx.x;
    int lane = tid & 31, w = tid >> 5;
    int c = blockIdx.x * 8 + w;

    for (int j = lane; j < P_NUM; j += 32)
        ws[w * P_NUM + j] = lw[c * P_NUM + j];
    __syncthreads();

    for (int n = 0; n < N_B; n++) {
        const float* a = &g_act[n * P_NUM];
        float s = 0.f;
        for (int j = lane; j < P_NUM; j += 32)
            s = fmaf(a[j], ws[w * P_NUM + j], s);
        #pragma unroll
        for (int off = 16; off > 0; off >>= 1)
            s += __shfl_xor_sync(0xffffffffu, s, off);
        if (lane == 0) out[n * N_CLS + c] = s;
    }
}

// ---------------------------------------------------------------------------
extern "C" void kernel_launch(void* const* d_in, const int* in_sizes, int n_in,
                              void* d_out, int out_size) {
    const float* x     = (const float*)d_in[0];
    const float* W1    = (const float*)d_in[1];
    const float* b1    = (const float*)d_in[2];
    const float* W2    = (const float*)d_in[3];
    const float* b2    = (const float*)d_in[4];
    const float* proto = (const float*)d_in[5];
    const float* lw    = (const float*)d_in[6];
    float* out = (float*)d_out;

    float* mind_out = (out_size >= N_B * N_CLS + N_B * P_NUM)
                          ? out + N_B * N_CLS : nullptr;

    cudaFuncSetAttribute(addon_kernel,
                         cudaFuncAttributeMaxDynamicSharedMemorySize, AD_TOT);
    cudaFuncSetAttribute(l2min_mma_kernel,
                         cudaFuncAttributeMaxDynamicSharedMemorySize, SM_TOT);
    cudaFuncSetAttribute(logits_kernel,
                         cudaFuncAttributeMaxDynamicSharedMemorySize,
                         8 * P_NUM * (int)sizeof(float));

    prep_kernel<<<256, 256>>>(W1, W2, proto);
    addon_kernel<<<dim3(L_LEN / 32, N_B), 256, AD_TOT>>>(x, b1, b2);
    l2min_mma_kernel<<<dim3(P_PAD / 128, N_B), 256, SM_TOT>>>(mind_out);
    logits_kernel<<<N_CLS / 8, 256, 8 * P_NUM * sizeof(float)>>>(lw, out);
}

// round 13
// speedup vs baseline: 1.4742x; 1.4742x over previous
#include <cuda_runtime.h>
#include <cuda_fp16.h>
#include <cstdint>
#include <math.h>

#define N_B   32
#define C_IN  128
#define L_LEN 512
#define C_P   64
#define P_NUM 2000
#define P_PAD 2048
#define N_CLS 200
#define EPS   1e-4f

// ---------------- scratch (no cudaMalloc allowed) --------------------------
__device__ float g_p2[P_PAD];                // ||proto||^2
__device__ float g_x2[N_B * L_LEN];          // per-position sum f^2
__device__ float g_w1t[C_IN * C_P];          // W1^T [c][o]
__device__ float g_w2t[C_P * C_P];           // W2^T [c][o]
__device__ float g_act[N_B * P_NUM];         // prototype activations
// fp16 split operands, K-major rows of 64 halves = 128B = 8 uint4
__device__ uint4 g_ph[P_PAD * 8];            // proto hi  [p][k]
__device__ uint4 g_pl[P_PAD * 8];            // proto lo
__device__ uint4 g_fh[N_B * L_LEN * 8];      // f hi      [n*l][k]
__device__ uint4 g_fl[N_B * L_LEN * 8];      // f lo

// ---------------- helpers ---------------------------------------------------
__device__ __forceinline__ uint32_t smem_u32(const void* p) {
    uint32_t a;
    asm("{ .reg .u64 t; cvta.to.shared.u64 t, %1; cvt.u32.u64 %0, t; }"
        : "=r"(a) : "l"(p));
    return a;
}
__device__ __forceinline__ void ldmx4(uint32_t* r, uint32_t addr) {
    asm volatile("ldmatrix.sync.aligned.m8n8.x4.shared.b16 {%0,%1,%2,%3}, [%4];"
                 : "=r"(r[0]), "=r"(r[1]), "=r"(r[2]), "=r"(r[3]) : "r"(addr));
}
__device__ __forceinline__ void mma16816(float* c, const uint32_t* a, const uint32_t* b) {
    asm volatile("mma.sync.aligned.m16n8k16.row.col.f32.f16.f16.f32 "
                 "{%0,%1,%2,%3}, {%4,%5,%6,%7}, {%8,%9}, {%0,%1,%2,%3};"
                 : "+f"(c[0]), "+f"(c[1]), "+f"(c[2]), "+f"(c[3])
                 : "r"(a[0]), "r"(a[1]), "r"(a[2]), "r"(a[3]), "r"(b[0]), "r"(b[1]));
}
__device__ __forceinline__ uint32_t pack_half2(float v0, float v1) {
    __half h0 = __float2half_rn(v0), h1 = __float2half_rn(v1);
    return (uint32_t)__half_as_ushort(h0) | ((uint32_t)__half_as_ushort(h1) << 16);
}
#define CP_ASYNC16(dst, src) \
    asm volatile("cp.async.cg.shared.global [%0], [%1], 16;" :: "r"(dst), "l"(src))
#define CP_COMMIT() asm volatile("cp.async.commit_group;")
#define CP_WAIT(n)  asm volatile("cp.async.wait_group %0;" :: "n"(n))

// ---------------------------------------------------------------------------
// Prep: W transposes, proto norms, proto fp16 hi/lo split
// ---------------------------------------------------------------------------
__global__ void prep_kernel(const float* __restrict__ W1,
                            const float* __restrict__ W2,
                            const float* __restrict__ proto) {
    int stride = gridDim.x * blockDim.x;
    int tid = blockIdx.x * blockDim.x + threadIdx.x;
    for (int e = tid; e < C_IN * C_P; e += stride) {
        int c = e >> 6, o = e & 63;
        g_w1t[e] = W1[o * C_IN + c];
    }
    for (int e = tid; e < C_P * C_P; e += stride) {
        int c = e >> 6, o = e & 63;
        g_w2t[e] = W2[o * C_P + c];
    }
    for (int p = tid; p < P_PAD; p += stride) {
        float s = 0.f;
        if (p < P_NUM) {
            #pragma unroll 8
            for (int c = 0; c < C_P; c++) {
                float v = proto[p * C_P + c];
                s += v * v;
            }
        }
        g_p2[p] = s;
    }
    for (int e = tid; e < P_PAD * 8; e += stride) {
        int p = e >> 3, u = e & 7;
        uint32_t hw[4], lw[4];
        #pragma unroll
        for (int j = 0; j < 4; j++) {
            float v0 = 0.f, v1 = 0.f;
            if (p < P_NUM) {
                v0 = proto[p * C_P + u * 8 + j * 2];
                v1 = proto[p * C_P + u * 8 + j * 2 + 1];
            }
            __half h0 = __float2half_rn(v0), h1 = __float2half_rn(v1);
            float r0 = v0 - __half2float(h0), r1 = v1 - __half2float(h1);
            hw[j] = (uint32_t)__half_as_ushort(h0) | ((uint32_t)__half_as_ushort(h1) << 16);
            lw[j] = pack_half2(r0, r1);
        }
        g_ph[e] = make_uint4(hw[0], hw[1], hw[2], hw[3]);
        g_pl[e] = make_uint4(lw[0], lw[1], lw[2], lw[3]);
    }
}

// ---------------------------------------------------------------------------
// addon: fused conv1(relu) -> conv2(sigmoid) -> fp16 hi/lo pack + x2
// grid (L/32 = 16, N_B), 256 threads. All intermediates stay in SMEM.
// ---------------------------------------------------------------------------
#define AD_XS  0
#define AD_W1  16384
#define AD_HS  49152
#define AD_W2  57344
#define AD_FS  73728
#define AD_TOT 81920

__global__ void __launch_bounds__(256) addon_kernel(const float* __restrict__ x,
                                                    const float* __restrict__ b1,
                                                    const float* __restrict__ b2) {
    extern __shared__ char sm[];
    float (*xs)[32]  = (float (*)[32])(sm + AD_XS);
    float (*w1s)[64] = (float (*)[64])(sm + AD_W1);
    float (*hs)[32]  = (float (*)[32])(sm + AD_HS);
    float (*w2s)[64] = (float (*)[64])(sm + AD_W2);
    float (*fs)[32]  = (float (*)[32])(sm + AD_FS);

    int n  = blockIdx.y;
    int l0 = blockIdx.x * 32;
    int tid = threadIdx.x;
    int tl = tid & 15, to = tid >> 4;

    for (int e = tid; e < C_IN * 32; e += 256) {
        int c = e >> 5, l = e & 31;
        xs[c][l] = x[(n * C_IN + c) * L_LEN + l0 + l];
    }
    for (int e = tid; e < C_IN * C_P; e += 256)
        w1s[e >> 6][e & 63] = g_w1t[e];
    for (int e = tid; e < C_P * C_P; e += 256)
        w2s[e >> 6][e & 63] = g_w2t[e];
    __syncthreads();

    // phase 1: h = relu(W1 @ x + b1)
    {
        float acc[4][2] = {};
        #pragma unroll
        for (int k = 0; k < C_IN; k++) {
            float4 a = *(const float4*)&w1s[k][to * 4];
            float2 b = *(const float2*)&xs[k][tl * 2];
            acc[0][0] += a.x * b.x; acc[0][1] += a.x * b.y;
            acc[1][0] += a.y * b.x; acc[1][1] += a.y * b.y;
            acc[2][0] += a.z * b.x; acc[2][1] += a.z * b.y;
            acc[3][0] += a.w * b.x; acc[3][1] += a.w * b.y;
        }
        float4 bv = *(const float4*)&b1[to * 4];
        float bb[4] = {bv.x, bv.y, bv.z, bv.w};
        #pragma unroll
        for (int i = 0; i < 4; i++) {
            hs[to * 4 + i][tl * 2]     = fmaxf(acc[i][0] + bb[i], 0.f);
            hs[to * 4 + i][tl * 2 + 1] = fmaxf(acc[i][1] + bb[i], 0.f);
        }
    }
    __syncthreads();

    // phase 2: f = sigmoid(W2 @ h + b2)
    {
        float acc[4][2] = {};
        #pragma unroll
        for (int k = 0; k < C_P; k++) {
            float4 a = *(const float4*)&w2s[k][to * 4];
            float2 b = *(const float2*)&hs[k][tl * 2];
            acc[0][0] += a.x * b.x; acc[0][1] += a.x * b.y;
            acc[1][0] += a.y * b.x; acc[1][1] += a.y * b.y;
            acc[2][0] += a.z * b.x; acc[2][1] += a.z * b.y;
            acc[3][0] += a.w * b.x; acc[3][1] += a.w * b.y;
        }
        float4 bv = *(const float4*)&b2[to * 4];
        float bb[4] = {bv.x, bv.y, bv.z, bv.w};
        #pragma unroll
        for (int i = 0; i < 4; i++) {
            float z0 = acc[i][0] + bb[i];
            float z1 = acc[i][1] + bb[i];
            fs[to * 4 + i][tl * 2]     = 1.f / (1.f + __expf(-z0));
            fs[to * 4 + i][tl * 2 + 1] = 1.f / (1.f + __expf(-z1));
        }
    }
    __syncthreads();

    // phase 3a: pack to fp16 hi/lo rows — all 256 threads, one (l,u) each
    {
        int l = tid & 31, u = tid >> 5;
        uint32_t hw[4], lw[4];
        #pragma unroll
        for (int j = 0; j < 4; j++) {
            float v0 = fs[u * 8 + j * 2][l];
            float v1 = fs[u * 8 + j * 2 + 1][l];
            __half h0 = __float2half_rn(v0), h1 = __float2half_rn(v1);
            float r0 = v0 - __half2float(h0), r1 = v1 - __half2float(h1);
            hw[j] = (uint32_t)__half_as_ushort(h0) |
                    ((uint32_t)__half_as_ushort(h1) << 16);
            lw[j] = pack_half2(r0, r1);
        }
        g_fh[(n * L_LEN + l0 + l) * 8 + u] = make_uint4(hw[0], hw[1], hw[2], hw[3]);
        g_fl[(n * L_LEN + l0 + l) * 8 + u] = make_uint4(lw[0], lw[1], lw[2], lw[3]);
    }

    // phase 3b: x2 per l (32 threads; deterministic fixed-order sum)
    if (tid < 32) {
        int l = tid;
        float s = 0.f;
        #pragma unroll
        for (int c = 0; c < C_P; c++) {
            float v = fs[c][l];
            s = fmaf(v, v, s);
        }
        g_x2[n * L_LEN + l0 + l] = s;
    }
}

// ---------------------------------------------------------------------------
// l2min via mma.sync: split-fp16 (pH·fH + pH·fL + pL·fH) + min over L
// grid (16, 32), 256 threads = 8 warps; block 128p x 128l, K=64
// cp.async 2-stage pipeline on B tiles.
// ---------------------------------------------------------------------------
#define ROW_B   144
#define SM_AH   0
#define SM_AL   18432
#define SM_B    36864
#define STAGE_B 36864
#define SM_MINB 110592
#define SM_TOT  111616

__global__ void __launch_bounds__(256, 1) l2min_mma_kernel(float* __restrict__ mind_out) {
    extern __shared__ char smem[];
    uint32_t sb = smem_u32(smem);
    float* minb = (float*)(smem + SM_MINB);   // [128][2]

    int tid = threadIdx.x;
    int lane = tid & 31, wid = tid >> 5;
    int warpP = wid & 3, warpL = wid >> 2;    // 4 p-warps x 2 l-warps
    int pt = blockIdx.x, n = blockIdx.y;

    // ---- A tiles (proto hi/lo): plain loads ----
    for (int e = tid; e < 1024; e += 256) {
        int row = e >> 3, u = e & 7;
        int off = row * ROW_B + u * 16;
        *(uint4*)(smem + SM_AH + off) = g_ph[(pt * 128 + row) * 8 + u];
        *(uint4*)(smem + SM_AL + off) = g_pl[(pt * 128 + row) * 8 + u];
    }

    // ---- B stage loader: 2048 x 16B via cp.async ----
    auto load_stage = [&](int lc, int st) {
        uint32_t dbase = sb + SM_B + st * STAGE_B;
        #pragma unroll
        for (int i = 0; i < 8; i++) {
            int e = tid + i * 256;
            int sel = e >> 10;            // 0 = hi, 1 = lo
            int e2 = e & 1023;
            int row = e2 >> 3, u = e2 & 7;
            uint32_t dst = dbase + sel * 18432 + row * ROW_B + u * 16;
            const uint4* src = (sel ? g_fl : g_fh) +
                               (n * L_LEN + lc * 128 + row) * 8 + u;
            CP_ASYNC16(dst, src);
        }
        CP_COMMIT();
    };
    load_stage(0, 0);

    // ldmatrix per-thread offsets
    int aRow = warpP * 32 + (lane & 7) + ((lane >> 3) & 1) * 8;
    int aCol = ((lane >> 4) & 1) * 8;
    uint32_t aOff = (uint32_t)(aRow * ROW_B + aCol * 2);
    int bRow = warpL * 64 + (lane & 7) + ((lane >> 4) & 1) * 8;
    int bCol = ((lane >> 3) & 1) * 8;
    uint32_t bOff = (uint32_t)(bRow * ROW_B + bCol * 2);

    float mind[2][2];
    mind[0][0] = mind[0][1] = mind[1][0] = mind[1][1] = 1e30f;

    for (int lc = 0; lc < 4; lc++) {
        if (lc < 3) { load_stage(lc + 1, (lc + 1) & 1); CP_WAIT(1); }
        else        { CP_WAIT(0); }
        __syncthreads();   // stage lc visible to all (also A on first iter)

        uint32_t sBH = sb + SM_B + (lc & 1) * STAGE_B;
        uint32_t sBL = sBH + 18432;

        float acc[2][8][4];
        #pragma unroll
        for (int mi = 0; mi < 2; mi++)
            #pragma unroll
            for (int ni = 0; ni < 8; ni++)
                #pragma unroll
                for (int q = 0; q < 4; q++) acc[mi][ni][q] = 0.f;

        #pragma unroll
        for (int ks = 0; ks < 4; ks++) {
            uint32_t ah[2][4], al[2][4];
            #pragma unroll
            for (int mi = 0; mi < 2; mi++) {
                uint32_t ao = aOff + mi * 16 * ROW_B + ks * 32;
                ldmx4(ah[mi], sb + SM_AH + ao);
                ldmx4(al[mi], sb + SM_AL + ao);
            }
            uint32_t bh[8][2], bl[8][2];
            #pragma unroll
            for (int nj = 0; nj < 4; nj++) {
                uint32_t bo = bOff + nj * 16 * ROW_B + ks * 32;
                uint32_t t[4];
                ldmx4(t, sBH + bo);
                bh[nj * 2][0] = t[0]; bh[nj * 2][1] = t[1];
                bh[nj * 2 + 1][0] = t[2]; bh[nj * 2 + 1][1] = t[3];
                ldmx4(t, sBL + bo);
                bl[nj * 2][0] = t[0]; bl[nj * 2][1] = t[1];
                bl[nj * 2 + 1][0] = t[2]; bl[nj * 2 + 1][1] = t[3];
            }
            #pragma unroll
            for (int mi = 0; mi < 2; mi++)
                #pragma unroll
                for (int ni = 0; ni < 8; ni++) {
                    mma16816(acc[mi][ni], ah[mi], bh[ni]);
                    mma16816(acc[mi][ni], ah[mi], bl[ni]);
                    mma16816(acc[mi][ni], al[mi], bh[ni]);
                }
        }

        // fold min_l(x2 - 2*xp)
        #pragma unroll
        for (int ni = 0; ni < 8; ni++) {
            float2 xv = __ldg((const float2*)&g_x2[n * L_LEN + lc * 128 +
                                                   warpL * 64 + ni * 8 + (lane & 3) * 2]);
            #pragma unroll
            for (int mi = 0; mi < 2; mi++) {
                float d0 = fmaf(-2.f, acc[mi][ni][0], xv.x);
                float d1 = fmaf(-2.f, acc[mi][ni][1], xv.y);
                float d2 = fmaf(-2.f, acc[mi][ni][2], xv.x);
                float d3 = fmaf(-2.f, acc[mi][ni][3], xv.y);
                mind[mi][0] = fminf(mind[mi][0], fminf(d0, d1));
                mind[mi][1] = fminf(mind[mi][1], fminf(d2, d3));
            }
        }
        __syncthreads();   // all reads of stage lc done before it is refilled
    }

    #pragma unroll
    for (int mi = 0; mi < 2; mi++)
        #pragma unroll
        for (int rh = 0; rh < 2; rh++) {
            float v = mind[mi][rh];
            v = fminf(v, __shfl_xor_sync(0xffffffffu, v, 1));
            v = fminf(v, __shfl_xor_sync(0xffffffffu, v, 2));
            mind[mi][rh] = v;
        }
    if ((lane & 3) == 0) {
        int rbase = warpP * 32 + (lane >> 2);
        minb[(rbase +  0) * 2 + warpL] = mind[0][0];
        minb[(rbase +  8) * 2 + warpL] = mind[0][1];
        minb[(rbase + 16) * 2 + warpL] = mind[1][0];
        minb[(rbase + 24) * 2 + warpL] = mind[1][1];
    }
    __syncthreads();

    if (tid < 128) {
        float m = fminf(minb[tid * 2], minb[tid * 2 + 1]);
        float p2v = g_p2[pt * 128 + tid];
        float d = fmaxf(m + p2v, 0.f);
        int p = pt * 128 + tid;
        if (p < P_NUM) {
            if (mind_out) mind_out[n * P_NUM + p] = d;
            g_act[n * P_NUM + p] = logf((d + 1.f) / (d + EPS));
        }
    }
}

// ---------------------------------------------------------------------------
// logits[n][c] = sum_p act[n][p] * last_w[c][p]
// grid (N_CLS, N_B), 64 threads — R4 measured-good form (parallelism-rich;
// lw/act are L2-resident, traffic is not the binder)
// ---------------------------------------------------------------------------
__global__ void logits_kernel(const float* __restrict__ lw, float* __restrict__ out) {
    int c = blockIdx.x, n = blockIdx.y;
    int tid = threadIdx.x;
    const float* a = &g_act[n * P_NUM];
    const float* w = &lw[c * P_NUM];
    float s = 0.f;
    for (int j = tid; j < P_NUM; j += 64)
        s += a[j] * w[j];
    #pragma unroll
    for (int off = 16; off > 0; off >>= 1)
        s += __shfl_xor_sync(0xffffffffu, s, off);
    __shared__ float red[2];
    if ((tid & 31) == 0) red[tid >> 5] = s;
    __syncthreads();
    if (tid == 0) out[n * N_CLS + c] = red[0] + red[1];
}

// ---------------------------------------------------------------------------
extern "C" void kernel_launch(void* const* d_in, const int* in_sizes, int n_in,
                              void* d_out, int out_size) {
    const float* x     = (const float*)d_in[0];
    const float* W1    = (const float*)d_in[1];
    const float* b1    = (const float*)d_in[2];
    const float* W2    = (const float*)d_in[3];
    const float* b2    = (const float*)d_in[4];
    const float* proto = (const float*)d_in[5];
    const float* lw    = (const float*)d_in[6];
    float* out = (float*)d_out;

    float* mind_out = (out_size >= N_B * N_CLS + N_B * P_NUM)
                          ? out + N_B * N_CLS : nullptr;

    cudaFuncSetAttribute(addon_kernel,
                         cudaFuncAttributeMaxDynamicSharedMemorySize, AD_TOT);
    cudaFuncSetAttribute(l2min_mma_kernel,
                         cudaFuncAttributeMaxDynamicSharedMemorySize, SM_TOT);

    prep_kernel<<<256, 256>>>(W1, W2, proto);
    addon_kernel<<<dim3(L_LEN / 32, N_B), 256, AD_TOT>>>(x, b1, b2);
    l2min_mma_kernel<<<dim3(P_PAD / 128, N_B), 256, SM_TOT>>>(mind_out);
    logits_kernel<<<dim3(N_CLS, N_B), 64>>>(lw, out);
}